// round 14
// baseline (speedup 1.0000x reference)
#include <cuda_runtime.h>
#include <cuda_fp16.h>
#include <cstdint>
#include <math.h>

// ---------------- problem constants ----------------
#define Bsz   8192
#define DIN   2048
#define H0    1024
#define H1    512
#define LAT   128
#define NC    8

#define TBM 128
#define BN  128
#define KC  64
#define NTHR 256
#define MAX_TILES 96
#define GRID_P 296            // 2 CTAs per SM

#define T_ROW  144            // 128B data + 16B pad per k-chunk row
#define A_SZ   (TBM * T_ROW)  // 18432
#define B_SZ   (BN * T_ROW)   // 18432
#define STAGE  (A_SZ + B_SZ)  // 36864
#define SMEM_BYTES (3 * STAGE) // 110592 per CTA; x2 CTAs = 221184 <= 227KB/SM

// ---------------- device scratch ----------------
__device__ __align__(16) __half g_xh  [Bsz * DIN];
__device__ __align__(16) float  g_epsp[Bsz * LAT];
__device__ __align__(16) __half g_h0h [Bsz * H0];
__device__ __align__(16) __half g_h1h [Bsz * H1];
__device__ __align__(16) __half g_zh  [Bsz * LAT];
__device__ __align__(16) __half g_d1h [Bsz * H1];
__device__ __align__(16) __half g_d2h [Bsz * H0];

// transposed fp16 weights [N, K] per cluster
__device__ __align__(16) __half g_we0[NC * DIN * H0];
__device__ __align__(16) __half g_we1[H0 * H1];
__device__ __align__(16) __half g_whd[256 * H1];       // interleaved: row 2j=mu_j, 2j+1=lv_j
__device__ __align__(16) __half g_wd0[H1 * LAT];
__device__ __align__(16) __half g_wd1[NC * H1 * H0];
__device__ __align__(16) __half g_wo [DIN * H0];

__device__ int g_segoff[NC + 1];
__device__ int g_fill[NC];
__device__ int g_perm[Bsz];

struct Tile { int row_start; int row_end; int cluster; };
__device__ Tile g_tiles[MAX_TILES];
__device__ int  g_ntiles;

// ---------------- helpers ----------------
__device__ __forceinline__ uint32_t smem_u32(const void* p) {
    return (uint32_t)__cvta_generic_to_shared(p);
}
__device__ __forceinline__ void cp16(uint32_t saddr, const void* gptr) {
    asm volatile("cp.async.cg.shared.global [%0], [%1], 16;"
                 :: "r"(saddr), "l"(__cvta_generic_to_global(gptr)) : "memory");
}
__device__ __forceinline__ void cp_commit() {
    asm volatile("cp.async.commit_group;" ::: "memory");
}
template<int N> __device__ __forceinline__ void cp_wait() {
    asm volatile("cp.async.wait_group %0;" :: "n"(N) : "memory");
}
__device__ __forceinline__ void ldsm4(uint32_t a, uint32_t* r) {
    asm volatile("ldmatrix.sync.aligned.m8n8.x4.shared.b16 {%0,%1,%2,%3}, [%4];"
                 : "=r"(r[0]), "=r"(r[1]), "=r"(r[2]), "=r"(r[3]) : "r"(a));
}
__device__ __forceinline__ void mma16816(float* c, const uint32_t* a, const uint32_t* b) {
    asm volatile("mma.sync.aligned.m16n8k16.row.col.f32.f16.f16.f32 "
                 "{%0,%1,%2,%3}, {%4,%5,%6,%7}, {%8,%9}, {%0,%1,%2,%3};"
                 : "+f"(c[0]), "+f"(c[1]), "+f"(c[2]), "+f"(c[3])
                 : "r"(a[0]), "r"(a[1]), "r"(a[2]), "r"(a[3]), "r"(b[0]), "r"(b[1]));
}

// ---------------- setup kernels ----------------
__global__ void histbuild_k(const int* __restrict__ labels) {
    __shared__ int scnt[NC];
    int t = threadIdx.x;
    if (t < NC) scnt[t] = 0;
    __syncthreads();
    for (int i = t; i < Bsz; i += NTHR) atomicAdd(&scnt[labels[i]], 1);
    __syncthreads();
    if (t == 0) {
        int off = 0;
        for (int c = 0; c < NC; c++) {
            g_segoff[c] = off; g_fill[c] = 0; off += scnt[c];
        }
        g_segoff[NC] = off;
        int tt = 0;
        for (int c = 0; c < NC; c++) {
            int s = g_segoff[c], e = g_segoff[c + 1];
            for (int r = s; r < e; r += TBM) {
                g_tiles[tt].row_start = r;
                g_tiles[tt].row_end   = min(r + TBM, e);
                g_tiles[tt].cluster   = c;
                tt++;
            }
        }
        g_ntiles = tt;
    }
}

// fused: compute permuted position for source row + gather/convert row
__global__ void scattergather_k(const int* __restrict__ labels,
                                const float* __restrict__ x, const float* __restrict__ eps) {
    __shared__ int spos;
    int r = blockIdx.x;
    if (threadIdx.x == 0) {
        int c = labels[r];
        int pos = g_segoff[c] + atomicAdd(&g_fill[c], 1);
        g_perm[pos] = r;
        spos = pos;
    }
    __syncthreads();
    int pos = spos;
    const float4* xs = reinterpret_cast<const float4*>(x + (size_t)r * DIN);
    size_t dbase = (size_t)pos * DIN;
    for (int j = threadIdx.x; j < DIN / 4; j += blockDim.x) {
        float4 v = xs[j];
        __half2* dh = reinterpret_cast<__half2*>(g_xh + dbase + 4 * (size_t)j);
        dh[0] = __floats2half2_rn(v.x, v.y);
        dh[1] = __floats2half2_rn(v.z, v.w);
    }
    if (threadIdx.x < LAT / 4) {
        reinterpret_cast<float4*>(g_epsp + (size_t)pos * LAT)[threadIdx.x] =
            reinterpret_cast<const float4*>(eps + (size_t)r * LAT)[threadIdx.x];
    }
}

// transpose + convert: W [K,N] fp32 -> Wt [N*rowmul, K] fp16, out row = n*rowmul+rowoff
__global__ void tsplit_k(const float* __restrict__ W,
                         __half* __restrict__ hi,
                         int K, int N, int rowmul, int rowoff) {
    __shared__ float t[32][33];
    int c = blockIdx.z;
    const float* Wc = W + (size_t)c * K * N;
    __half* hic = hi + (size_t)c * K * N * rowmul;   // rowmul>1 only for single-cluster calls
    int n0 = blockIdx.x * 32, k0 = blockIdx.y * 32;
    int tx = threadIdx.x;
    for (int i = threadIdx.y; i < 32; i += 8)
        t[i][tx] = Wc[(size_t)(k0 + i) * N + n0 + tx];
    __syncthreads();
    for (int i = threadIdx.y; i < 32; i += 8) {
        size_t o = (size_t)((n0 + i) * rowmul + rowoff) * K + k0 + tx;
        hic[o] = __float2half(t[tx][i]);
    }
}

// ---------------- persistent HMMA fp16 GEMM, 2 CTAs/SM ----------------
// CTA tile 128x128, 8 warps (4m x 2n, warp 32x64), 3-stage cp.async pipeline.
// EPI: 0 = relu + fp16 store; 1 = fused heads (mu/lv interleaved cols -> z,out);
//      2 = +bias, scatter fp32 to out
template<int EPI, bool GROUPED>
__global__ __launch_bounds__(NTHR, 2)
void hmma_gemm_k(const __half* __restrict__ A, int lda,
                 const __half* __restrict__ W, size_t wstride,
                 const float* __restrict__ bias, const float* __restrict__ bias2, int bstride,
                 int N, int K, int mtiles_in,
                 __half* __restrict__ O, int ldo,
                 float* __restrict__ out)
{
    extern __shared__ char smem[];
    uint32_t sb = smem_u32(smem);
    int tid  = threadIdx.x;
    int lane = tid & 31;
    int wid  = tid >> 5;
    int wm = (wid >> 1) * 32;    // 4 warps in m (tile 128)
    int wn = (wid & 1) * 64;     // 2 warps in n (tile 128)

    int mtiles = GROUPED ? g_ntiles : mtiles_in;
    int ncols  = N / BN;
    int total  = ncols * mtiles;
    int nk = K / KC;

    int arow = ((lane >> 3) & 1) * 8 + (lane & 7);
    int acol = (lane >> 4) * 16;
    int brow = ((lane >> 4) & 1) * 8 + (lane & 7);
    int bcol = ((lane >> 3) & 1) * 16;

    for (int t = blockIdx.x; t < total; t += gridDim.x) {
        int ncol = t / mtiles;
        int mti  = t - ncol * mtiles;
        int row0, row_end, c;
        if (GROUPED) {
            Tile tl = g_tiles[mti];
            row0 = tl.row_start; row_end = tl.row_end; c = tl.cluster;
        } else {
            row0 = mti * TBM; row_end = row0 + TBM; c = 0;
        }
        int n0 = ncol * BN;

        const __half* Wc = W + (size_t)c * wstride;

        float acc[2][8][4];
        #pragma unroll
        for (int a = 0; a < 2; a++)
            #pragma unroll
            for (int b = 0; b < 8; b++)
                #pragma unroll
                for (int d = 0; d < 4; d++) acc[a][b][d] = 0.f;

        auto issue = [&](int i) {
            int st = i % 3;
            uint32_t base = sb + (uint32_t)st * STAGE;
            int k0 = i * KC;
            // A: 128 rows x 8 chunks of 16B
            #pragma unroll
            for (int it = 0; it < 4; it++) {
                int chunk = tid + it * NTHR;
                int row = chunk >> 3, c16 = chunk & 7;
                uint32_t soff = (uint32_t)(row * T_ROW + c16 * 16);
                int gr = row0 + row;
                if (GROUPED && gr >= Bsz) gr = Bsz - 1;
                size_t ga = (size_t)gr * lda + k0 + c16 * 8;
                cp16(base + soff, A + ga);
            }
            // B: 128 rows x 8 chunks
            #pragma unroll
            for (int it = 0; it < 4; it++) {
                int chunk = tid + it * NTHR;
                int row = chunk >> 3, c16 = chunk & 7;
                uint32_t soff = (uint32_t)(row * T_ROW + c16 * 16);
                size_t gb = (size_t)(n0 + row) * K + k0 + c16 * 8;
                cp16(base + A_SZ + soff, Wc + gb);
            }
            cp_commit();
        };

        issue(0);
        if (nk > 1) issue(1);

        for (int i = 0; i < nk; i++) {
            if (i == nk - 1) cp_wait<0>(); else cp_wait<1>();
            // barrier: data of chunk i visible; all warps done with chunk i-1
            // -> safe for issue(i+2) to overwrite stage (i+2)%3 == (i-1)%3
            __syncthreads();
            if (i + 2 < nk) issue(i + 2);
            uint32_t base = sb + (uint32_t)(i % 3) * STAGE;

            #pragma unroll
            for (int kk = 0; kk < KC / 16; kk++) {
                uint32_t ah[2][4], bh[4][4];
                #pragma unroll
                for (int mt = 0; mt < 2; mt++) {
                    uint32_t ra = base + (uint32_t)((wm + mt * 16 + arow) * T_ROW + kk * 32 + acol);
                    ldsm4(ra, ah[mt]);
                }
                #pragma unroll
                for (int p = 0; p < 4; p++) {
                    uint32_t rb = base + A_SZ + (uint32_t)((wn + p * 16 + brow) * T_ROW + kk * 32 + bcol);
                    ldsm4(rb, bh[p]);
                }
                #pragma unroll
                for (int mt = 0; mt < 2; mt++)
                    #pragma unroll
                    for (int p = 0; p < 4; p++) {
                        mma16816(acc[mt][2 * p],     ah[mt], &bh[p][0]);
                        mma16816(acc[mt][2 * p + 1], ah[mt], &bh[p][2]);
                    }
            }
        }

        // ---------------- epilogue (registers + global only) ----------------
        int gid = lane >> 2, tig = lane & 3;
        const float* bc = bias + c * bstride;

        #pragma unroll
        for (int mt = 0; mt < 2; mt++) {
            int mA = row0 + wm + mt * 16 + gid;
            int mB = mA + 8;
            bool vA = !GROUPED || (mA < row_end);
            bool vB = !GROUPED || (mB < row_end);
            int oA = 0, oB = 0;
            if (EPI == 1 || EPI == 2) { oA = g_perm[mA]; oB = g_perm[mB]; }

            #pragma unroll
            for (int nt = 0; nt < 8; nt++) {
                int n = n0 + wn + nt * 8 + 2 * tig;
                float* a = acc[mt][nt];
                if (EPI == 0) {
                    float b0 = bc[n], b1 = bc[n + 1];
                    if (vA) {
                        float v0 = fmaxf(a[0] + b0, 0.f), v1 = fmaxf(a[1] + b1, 0.f);
                        *reinterpret_cast<__half2*>(O + (size_t)mA * ldo + n) = __floats2half2_rn(v0, v1);
                    }
                    if (vB) {
                        float v2 = fmaxf(a[2] + b0, 0.f), v3 = fmaxf(a[3] + b1, 0.f);
                        *reinterpret_cast<__half2*>(O + (size_t)mB * ldo + n) = __floats2half2_rn(v2, v3);
                    }
                } else if (EPI == 1) {
                    // n is even; cols (n, n+1) = (mu_j, lv_j), j = n>>1
                    int j = n >> 1;
                    float bmu = bias[j], blv = bias2[j];
                    size_t OFF_MU = (size_t)Bsz * DIN;
                    size_t OFF_LV = OFF_MU + (size_t)Bsz * LAT;
                    {
                        float mu = a[0] + bmu;
                        float lv = a[1] + blv;
                        float z  = mu + g_epsp[(size_t)mA * LAT + j] * expf(0.5f * lv);
                        g_zh[(size_t)mA * LAT + j] = __float2half(z);
                        __stcs(out + OFF_MU + (size_t)oA * LAT + j, mu);
                        __stcs(out + OFF_LV + (size_t)oA * LAT + j, lv);
                    }
                    {
                        float mu = a[2] + bmu;
                        float lv = a[3] + blv;
                        float z  = mu + g_epsp[(size_t)mB * LAT + j] * expf(0.5f * lv);
                        g_zh[(size_t)mB * LAT + j] = __float2half(z);
                        __stcs(out + OFF_MU + (size_t)oB * LAT + j, mu);
                        __stcs(out + OFF_LV + (size_t)oB * LAT + j, lv);
                    }
                } else {
                    float b0 = bc[n], b1 = bc[n + 1];
                    float2 p0; p0.x = a[0] + b0; p0.y = a[1] + b1;
                    float2 p1; p1.x = a[2] + b0; p1.y = a[3] + b1;
                    __stcs(reinterpret_cast<float2*>(out + (size_t)oA * DIN + n), p0);
                    __stcs(reinterpret_cast<float2*>(out + (size_t)oB * DIN + n), p1);
                }
            }
        }
        // stage-reuse guard before next tile's prefetch
        __syncthreads();
    }
}

// ---------------- launcher ----------------
extern "C" void kernel_launch(void* const* d_in, const int* in_sizes, int n_in,
                              void* d_out, int out_size)
{
    const float* x        = (const float*)d_in[0];
    const int*   labels   = (const int*)  d_in[1];
    const float* eps      = (const float*)d_in[2];
    const float* W_enc0   = (const float*)d_in[3];
    const float* b_enc0   = (const float*)d_in[4];
    const float* W_enc1   = (const float*)d_in[5];
    const float* b_enc1   = (const float*)d_in[6];
    const float* W_mu     = (const float*)d_in[7];
    const float* b_mu     = (const float*)d_in[8];
    const float* W_logvar = (const float*)d_in[9];
    const float* b_logvar = (const float*)d_in[10];
    const float* W_dec0   = (const float*)d_in[11];
    const float* b_dec0   = (const float*)d_in[12];
    const float* W_dec1   = (const float*)d_in[13];
    const float* b_dec1   = (const float*)d_in[14];
    const float* W_out    = (const float*)d_in[15];
    const float* b_out    = (const float*)d_in[16];
    float* out = (float*)d_out;

    __half *xh, *h0h, *h1h, *zh, *d1h, *d2h;
    __half *we0, *we1, *whd, *wd0, *wd1, *wo;
    cudaGetSymbolAddress((void**)&xh, g_xh);
    cudaGetSymbolAddress((void**)&h0h, g_h0h);
    cudaGetSymbolAddress((void**)&h1h, g_h1h);
    cudaGetSymbolAddress((void**)&zh, g_zh);
    cudaGetSymbolAddress((void**)&d1h, g_d1h);
    cudaGetSymbolAddress((void**)&d2h, g_d2h);
    cudaGetSymbolAddress((void**)&we0, g_we0);
    cudaGetSymbolAddress((void**)&we1, g_we1);
    cudaGetSymbolAddress((void**)&whd, g_whd);
    cudaGetSymbolAddress((void**)&wd0, g_wd0);
    cudaGetSymbolAddress((void**)&wd1, g_wd1);
    cudaGetSymbolAddress((void**)&wo, g_wo);

    cudaFuncSetAttribute(hmma_gemm_k<0, true>,  cudaFuncAttributeMaxDynamicSharedMemorySize, SMEM_BYTES);
    cudaFuncSetAttribute(hmma_gemm_k<0, false>, cudaFuncAttributeMaxDynamicSharedMemorySize, SMEM_BYTES);
    cudaFuncSetAttribute(hmma_gemm_k<1, false>, cudaFuncAttributeMaxDynamicSharedMemorySize, SMEM_BYTES);
    cudaFuncSetAttribute(hmma_gemm_k<2, false>, cudaFuncAttributeMaxDynamicSharedMemorySize, SMEM_BYTES);

    // lazy static stream/events (created on uncaptured correctness call)
    static cudaStream_t s2 = nullptr;
    static cudaEvent_t ev_start = nullptr, ev_we0 = nullptr, ev_rest = nullptr;
    if (!s2) {
        cudaStreamCreateWithFlags(&s2, cudaStreamNonBlocking);
        cudaEventCreateWithFlags(&ev_start, cudaEventDisableTiming);
        cudaEventCreateWithFlags(&ev_we0,   cudaEventDisableTiming);
        cudaEventCreateWithFlags(&ev_rest,  cudaEventDisableTiming);
    }

    // fork: weight conversions on s2, routing/gather on default stream
    cudaEventRecord(ev_start, 0);
    cudaStreamWaitEvent(s2, ev_start, 0);

    tsplit_k<<<dim3(H0 / 32, DIN / 32, NC), dim3(32, 8), 0, s2>>>(W_enc0, we0, DIN, H0, 1, 0);
    cudaEventRecord(ev_we0, s2);
    tsplit_k<<<dim3(H0 / 32, H1 / 32, NC), dim3(32, 8), 0, s2>>>(W_dec1, wd1, H1, H0, 1, 0);
    tsplit_k<<<dim3(H1 / 32, H0 / 32, 1), dim3(32, 8), 0, s2>>>(W_enc1, we1, H0, H1, 1, 0);
    tsplit_k<<<dim3(LAT / 32, H1 / 32, 1), dim3(32, 8), 0, s2>>>(W_mu, whd, H1, LAT, 2, 0);
    tsplit_k<<<dim3(LAT / 32, H1 / 32, 1), dim3(32, 8), 0, s2>>>(W_logvar, whd, H1, LAT, 2, 1);
    tsplit_k<<<dim3(H1 / 32, LAT / 32, 1), dim3(32, 8), 0, s2>>>(W_dec0, wd0, LAT, H1, 1, 0);
    tsplit_k<<<dim3(DIN / 32, H0 / 32, 1), dim3(32, 8), 0, s2>>>(W_out, wo, H0, DIN, 1, 0);
    cudaEventRecord(ev_rest, s2);

    histbuild_k<<<1, NTHR>>>(labels);
    scattergather_k<<<Bsz, 128>>>(labels, x, eps);

    // encoder layer 0 (grouped) — needs we0 + gather
    cudaStreamWaitEvent(0, ev_we0, 0);
    hmma_gemm_k<0, true><<<GRID_P, NTHR, SMEM_BYTES>>>(
        xh, DIN, we0, (size_t)DIN * H0, b_enc0, nullptr, H0,
        H0, DIN, 0, h0h, H0, nullptr);

    // join remaining conversions
    cudaStreamWaitEvent(0, ev_rest, 0);

    // encoder layer 1
    hmma_gemm_k<0, false><<<GRID_P, NTHR, SMEM_BYTES>>>(
        h0h, H0, we1, 0, b_enc1, nullptr, 0,
        H1, H0, Bsz / TBM, h1h, H1, nullptr);

    // heads (fused latent): interleaved mu/lv cols; epilogue computes z + scatters mu/lv
    hmma_gemm_k<1, false><<<GRID_P, NTHR, SMEM_BYTES>>>(
        h1h, H1, whd, 0, b_mu, b_logvar, 0,
        256, H1, Bsz / TBM, nullptr, 0, out);

    // decoder layer 0
    hmma_gemm_k<0, false><<<GRID_P, NTHR, SMEM_BYTES>>>(
        zh, LAT, wd0, 0, b_dec0, nullptr, 0,
        H1, LAT, Bsz / TBM, d1h, H1, nullptr);

    // decoder layer 1 (grouped)
    hmma_gemm_k<0, true><<<GRID_P, NTHR, SMEM_BYTES>>>(
        d1h, H1, wd1, (size_t)H1 * H0, b_dec1, nullptr, H0,
        H0, H1, 0, d2h, H0, nullptr);

    // output layer (scatter rows)
    hmma_gemm_k<2, false><<<GRID_P, NTHR, SMEM_BYTES>>>(
        d2h, H0, wo, 0, b_out, nullptr, 0,
        DIN, H0, Bsz / TBM, nullptr, 0, out);

    (void)in_sizes; (void)n_in; (void)out_size;
}

// round 15
// speedup vs baseline: 1.5085x; 1.5085x over previous
#include <cuda_runtime.h>
#include <cuda_fp16.h>
#include <cstdint>
#include <math.h>

// ---------------- problem constants ----------------
#define Bsz   8192
#define DIN   2048
#define H0    1024
#define H1    512
#define LAT   128
#define NC    8

#define TBM 128
#define BN  128
#define KC  64
#define NTHR 256
#define MAX_TILES 96
#define GRID_P 296            // 2 CTAs per SM

#define T_ROW  144            // 128B data + 16B pad per k-chunk row
#define A_SZ   (TBM * T_ROW)  // 18432
#define B_SZ   (BN * T_ROW)   // 18432
#define STAGE  (A_SZ + B_SZ)  // 36864
#define SMEM_BYTES (3 * STAGE) // 110592 per CTA; x2 CTAs = 221184 <= 227KB/SM

// ---------------- device scratch ----------------
__device__ __align__(16) __half g_xh  [Bsz * DIN];
__device__ __align__(16) float  g_epsp[Bsz * LAT];
__device__ __align__(16) __half g_h0h [Bsz * H0];
__device__ __align__(16) __half g_h1h [Bsz * H1];
__device__ __align__(16) float  g_hd  [Bsz * 256];     // mu|logvar raw (permuted rows)
__device__ __align__(16) __half g_zh  [Bsz * LAT];
__device__ __align__(16) __half g_d1h [Bsz * H1];
__device__ __align__(16) __half g_d2h [Bsz * H0];

// transposed fp16 weights [N, K] per cluster
__device__ __align__(16) __half g_we0[NC * DIN * H0];
__device__ __align__(16) __half g_we1[H0 * H1];
__device__ __align__(16) __half g_whd[256 * H1];       // [mu;logvar] concat rows
__device__ __align__(16) __half g_wd0[H1 * LAT];
__device__ __align__(16) __half g_wd1[NC * H1 * H0];
__device__ __align__(16) __half g_wo [DIN * H0];

__device__ int g_segoff[NC + 1];
__device__ int g_fill[NC];
__device__ int g_perm[Bsz];

struct Tile { int row_start; int row_end; int cluster; };
__device__ Tile g_tiles[MAX_TILES];
__device__ int  g_ntiles;

// ---------------- helpers ----------------
__device__ __forceinline__ uint32_t smem_u32(const void* p) {
    return (uint32_t)__cvta_generic_to_shared(p);
}
__device__ __forceinline__ void cp16(uint32_t saddr, const void* gptr) {
    asm volatile("cp.async.cg.shared.global [%0], [%1], 16;"
                 :: "r"(saddr), "l"(__cvta_generic_to_global(gptr)) : "memory");
}
__device__ __forceinline__ void cp_commit() {
    asm volatile("cp.async.commit_group;" ::: "memory");
}
template<int N> __device__ __forceinline__ void cp_wait() {
    asm volatile("cp.async.wait_group %0;" :: "n"(N) : "memory");
}
__device__ __forceinline__ void ldsm4(uint32_t a, uint32_t* r) {
    asm volatile("ldmatrix.sync.aligned.m8n8.x4.shared.b16 {%0,%1,%2,%3}, [%4];"
                 : "=r"(r[0]), "=r"(r[1]), "=r"(r[2]), "=r"(r[3]) : "r"(a));
}
__device__ __forceinline__ void mma16816(float* c, const uint32_t* a, const uint32_t* b) {
    asm volatile("mma.sync.aligned.m16n8k16.row.col.f32.f16.f16.f32 "
                 "{%0,%1,%2,%3}, {%4,%5,%6,%7}, {%8,%9}, {%0,%1,%2,%3};"
                 : "+f"(c[0]), "+f"(c[1]), "+f"(c[2]), "+f"(c[3])
                 : "r"(a[0]), "r"(a[1]), "r"(a[2]), "r"(a[3]), "r"(b[0]), "r"(b[1]));
}

// ---------------- setup kernels ----------------
__global__ void histbuild_k(const int* __restrict__ labels) {
    __shared__ int scnt[NC];
    int t = threadIdx.x;
    if (t < NC) scnt[t] = 0;
    __syncthreads();
    for (int i = t; i < Bsz; i += NTHR) atomicAdd(&scnt[labels[i]], 1);
    __syncthreads();
    if (t == 0) {
        int off = 0;
        for (int c = 0; c < NC; c++) {
            g_segoff[c] = off; g_fill[c] = 0; off += scnt[c];
        }
        g_segoff[NC] = off;
        int tt = 0;
        for (int c = 0; c < NC; c++) {
            int s = g_segoff[c], e = g_segoff[c + 1];
            for (int r = s; r < e; r += TBM) {
                g_tiles[tt].row_start = r;
                g_tiles[tt].row_end   = min(r + TBM, e);
                g_tiles[tt].cluster   = c;
                tt++;
            }
        }
        g_ntiles = tt;
    }
}

// fused: compute permuted position for source row + gather/convert row
__global__ void scattergather_k(const int* __restrict__ labels,
                                const float* __restrict__ x, const float* __restrict__ eps) {
    __shared__ int spos;
    int r = blockIdx.x;
    if (threadIdx.x == 0) {
        int c = labels[r];
        int pos = g_segoff[c] + atomicAdd(&g_fill[c], 1);
        g_perm[pos] = r;
        spos = pos;
    }
    __syncthreads();
    int pos = spos;
    const float4* xs = reinterpret_cast<const float4*>(x + (size_t)r * DIN);
    size_t dbase = (size_t)pos * DIN;
    for (int j = threadIdx.x; j < DIN / 4; j += blockDim.x) {
        float4 v = xs[j];
        __half2* dh = reinterpret_cast<__half2*>(g_xh + dbase + 4 * (size_t)j);
        dh[0] = __floats2half2_rn(v.x, v.y);
        dh[1] = __floats2half2_rn(v.z, v.w);
    }
    if (threadIdx.x < LAT / 4) {
        reinterpret_cast<float4*>(g_epsp + (size_t)pos * LAT)[threadIdx.x] =
            reinterpret_cast<const float4*>(eps + (size_t)r * LAT)[threadIdx.x];
    }
}

// transpose + convert: W [K,N] fp32 -> Wt [N,K] fp16 (C matrices via blockIdx.z)
__global__ void tsplit_k(const float* __restrict__ W,
                         __half* __restrict__ hi,
                         int K, int N) {
    __shared__ float t[32][33];
    int c = blockIdx.z;
    const float* Wc = W + (size_t)c * K * N;
    __half* hic = hi + (size_t)c * K * N;
    int n0 = blockIdx.x * 32, k0 = blockIdx.y * 32;
    int tx = threadIdx.x;
    for (int i = threadIdx.y; i < 32; i += 8)
        t[i][tx] = Wc[(size_t)(k0 + i) * N + n0 + tx];
    __syncthreads();
    for (int i = threadIdx.y; i < 32; i += 8) {
        size_t o = (size_t)(n0 + i) * K + k0 + tx;
        hic[o] = __float2half(t[tx][i]);
    }
}

// ---------------- persistent HMMA fp16 GEMM, 2 CTAs/SM ----------------
// CTA tile 128x128, 8 warps (4m x 2n, warp 32x64), 3-stage cp.async pipeline.
// EPI: 0 = relu + fp16 store; 1 = raw fp32 to g_hd; 2 = +bias, scatter fp32 to out
template<int EPI, bool GROUPED>
__global__ __launch_bounds__(NTHR, 2)
void hmma_gemm_k(const __half* __restrict__ A, int lda,
                 const __half* __restrict__ W, size_t wstride,
                 const float* __restrict__ bias, int bstride,
                 int N, int K, int mtiles_in,
                 __half* __restrict__ O, int ldo,
                 float* __restrict__ out)
{
    extern __shared__ char smem[];
    uint32_t sb = smem_u32(smem);
    int tid  = threadIdx.x;
    int lane = tid & 31;
    int wid  = tid >> 5;
    int wm = (wid >> 1) * 32;    // 4 warps in m (tile 128)
    int wn = (wid & 1) * 64;     // 2 warps in n (tile 128)

    int mtiles = GROUPED ? g_ntiles : mtiles_in;
    int ncols  = N / BN;
    int total  = ncols * mtiles;
    int nk = K / KC;

    int arow = ((lane >> 3) & 1) * 8 + (lane & 7);
    int acol = (lane >> 4) * 16;
    int brow = ((lane >> 4) & 1) * 8 + (lane & 7);
    int bcol = ((lane >> 3) & 1) * 16;

    for (int t = blockIdx.x; t < total; t += gridDim.x) {
        int ncol = t / mtiles;
        int mti  = t - ncol * mtiles;
        int row0, row_end, c;
        if (GROUPED) {
            Tile tl = g_tiles[mti];
            row0 = tl.row_start; row_end = tl.row_end; c = tl.cluster;
        } else {
            row0 = mti * TBM; row_end = row0 + TBM; c = 0;
        }
        int n0 = ncol * BN;

        const __half* Wc = W + (size_t)c * wstride;

        float acc[2][8][4];
        #pragma unroll
        for (int a = 0; a < 2; a++)
            #pragma unroll
            for (int b = 0; b < 8; b++)
                #pragma unroll
                for (int d = 0; d < 4; d++) acc[a][b][d] = 0.f;

        auto issue = [&](int i) {
            int st = i % 3;
            uint32_t base = sb + (uint32_t)st * STAGE;
            int k0 = i * KC;
            // A: 128 rows x 8 chunks of 16B
            #pragma unroll
            for (int it = 0; it < 4; it++) {
                int chunk = tid + it * NTHR;
                int row = chunk >> 3, c16 = chunk & 7;
                uint32_t soff = (uint32_t)(row * T_ROW + c16 * 16);
                int gr = row0 + row;
                if (GROUPED && gr >= Bsz) gr = Bsz - 1;
                size_t ga = (size_t)gr * lda + k0 + c16 * 8;
                cp16(base + soff, A + ga);
            }
            // B: 128 rows x 8 chunks
            #pragma unroll
            for (int it = 0; it < 4; it++) {
                int chunk = tid + it * NTHR;
                int row = chunk >> 3, c16 = chunk & 7;
                uint32_t soff = (uint32_t)(row * T_ROW + c16 * 16);
                size_t gb = (size_t)(n0 + row) * K + k0 + c16 * 8;
                cp16(base + A_SZ + soff, Wc + gb);
            }
            cp_commit();
        };

        issue(0);
        if (nk > 1) issue(1);

        for (int i = 0; i < nk; i++) {
            if (i == nk - 1) cp_wait<0>(); else cp_wait<1>();
            // barrier: data of chunk i visible; all warps done with chunk i-1
            // -> safe for issue(i+2) to overwrite stage (i+2)%3 == (i-1)%3
            __syncthreads();
            if (i + 2 < nk) issue(i + 2);
            uint32_t base = sb + (uint32_t)(i % 3) * STAGE;

            #pragma unroll
            for (int kk = 0; kk < KC / 16; kk++) {
                uint32_t ah[2][4], bh[4][4];
                #pragma unroll
                for (int mt = 0; mt < 2; mt++) {
                    uint32_t ra = base + (uint32_t)((wm + mt * 16 + arow) * T_ROW + kk * 32 + acol);
                    ldsm4(ra, ah[mt]);
                }
                #pragma unroll
                for (int p = 0; p < 4; p++) {
                    uint32_t rb = base + A_SZ + (uint32_t)((wn + p * 16 + brow) * T_ROW + kk * 32 + bcol);
                    ldsm4(rb, bh[p]);
                }
                #pragma unroll
                for (int mt = 0; mt < 2; mt++)
                    #pragma unroll
                    for (int p = 0; p < 4; p++) {
                        mma16816(acc[mt][2 * p],     ah[mt], &bh[p][0]);
                        mma16816(acc[mt][2 * p + 1], ah[mt], &bh[p][2]);
                    }
            }
        }

        // ---------------- epilogue (registers + global only) ----------------
        int gid = lane >> 2, tig = lane & 3;
        const float* bc = bias + c * bstride;

        #pragma unroll
        for (int mt = 0; mt < 2; mt++) {
            int mA = row0 + wm + mt * 16 + gid;
            int mB = mA + 8;
            bool vA = !GROUPED || (mA < row_end);
            bool vB = !GROUPED || (mB < row_end);
            int oA = 0, oB = 0;
            if (EPI == 2) { oA = g_perm[mA]; oB = g_perm[mB]; }

            #pragma unroll
            for (int nt = 0; nt < 8; nt++) {
                int n = n0 + wn + nt * 8 + 2 * tig;
                float* a = acc[mt][nt];
                if (EPI == 0) {
                    float b0 = bc[n], b1 = bc[n + 1];
                    if (vA) {
                        float v0 = fmaxf(a[0] + b0, 0.f), v1 = fmaxf(a[1] + b1, 0.f);
                        *reinterpret_cast<__half2*>(O + (size_t)mA * ldo + n) = __floats2half2_rn(v0, v1);
                    }
                    if (vB) {
                        float v2 = fmaxf(a[2] + b0, 0.f), v3 = fmaxf(a[3] + b1, 0.f);
                        *reinterpret_cast<__half2*>(O + (size_t)mB * ldo + n) = __floats2half2_rn(v2, v3);
                    }
                } else if (EPI == 1) {
                    float2 p0; p0.x = a[0]; p0.y = a[1];
                    float2 p1; p1.x = a[2]; p1.y = a[3];
                    *reinterpret_cast<float2*>(&g_hd[(size_t)mA * 256 + n]) = p0;
                    *reinterpret_cast<float2*>(&g_hd[(size_t)mB * 256 + n]) = p1;
                } else {
                    float b0 = bc[n], b1 = bc[n + 1];
                    float2 p0; p0.x = a[0] + b0; p0.y = a[1] + b1;
                    float2 p1; p1.x = a[2] + b0; p1.y = a[3] + b1;
                    __stcs(reinterpret_cast<float2*>(out + (size_t)oA * DIN + n), p0);
                    __stcs(reinterpret_cast<float2*>(out + (size_t)oB * DIN + n), p1);
                }
            }
        }
        // stage-reuse guard before next tile's prefetch
        __syncthreads();
    }
}

// ---------------- latent: bias + reparameterize + scatter mu/logvar, z->fp16 ----
// vectorized: 4 latent elems per thread (float4 over g_hd / g_epsp)
__global__ void latent_k(const float* __restrict__ bmu, const float* __restrict__ blv,
                         float* __restrict__ out) {
    int idx = blockIdx.x * blockDim.x + threadIdx.x;   // over Bsz*LAT/4
    if (idx >= Bsz * LAT / 4) return;
    int r  = idx >> 5;          // LAT/4 = 32 quads per row
    int q  = idx & 31;
    int j  = q * 4;
    float4 mu4 = *reinterpret_cast<const float4*>(&g_hd[(size_t)r * 256 + j]);
    float4 lv4 = *reinterpret_cast<const float4*>(&g_hd[(size_t)r * 256 + 128 + j]);
    float4 bm  = *reinterpret_cast<const float4*>(bmu + j);
    float4 bl  = *reinterpret_cast<const float4*>(blv + j);
    float4 ep  = *reinterpret_cast<const float4*>(&g_epsp[(size_t)r * LAT + j]);
    mu4.x += bm.x; mu4.y += bm.y; mu4.z += bm.z; mu4.w += bm.w;
    lv4.x += bl.x; lv4.y += bl.y; lv4.z += bl.z; lv4.w += bl.w;
    float z0 = mu4.x + ep.x * expf(0.5f * lv4.x);
    float z1 = mu4.y + ep.y * expf(0.5f * lv4.y);
    float z2 = mu4.z + ep.z * expf(0.5f * lv4.z);
    float z3 = mu4.w + ep.w * expf(0.5f * lv4.w);
    __half2* zp = reinterpret_cast<__half2*>(&g_zh[(size_t)r * LAT + j]);
    zp[0] = __floats2half2_rn(z0, z1);
    zp[1] = __floats2half2_rn(z2, z3);
    int orow = g_perm[r];
    size_t OFF_MU = (size_t)Bsz * DIN;
    size_t OFF_LV = OFF_MU + (size_t)Bsz * LAT;
    *reinterpret_cast<float4*>(out + OFF_MU + (size_t)orow * LAT + j) = mu4;
    *reinterpret_cast<float4*>(out + OFF_LV + (size_t)orow * LAT + j) = lv4;
}

// ---------------- launcher ----------------
extern "C" void kernel_launch(void* const* d_in, const int* in_sizes, int n_in,
                              void* d_out, int out_size)
{
    const float* x        = (const float*)d_in[0];
    const int*   labels   = (const int*)  d_in[1];
    const float* eps      = (const float*)d_in[2];
    const float* W_enc0   = (const float*)d_in[3];
    const float* b_enc0   = (const float*)d_in[4];
    const float* W_enc1   = (const float*)d_in[5];
    const float* b_enc1   = (const float*)d_in[6];
    const float* W_mu     = (const float*)d_in[7];
    const float* b_mu     = (const float*)d_in[8];
    const float* W_logvar = (const float*)d_in[9];
    const float* b_logvar = (const float*)d_in[10];
    const float* W_dec0   = (const float*)d_in[11];
    const float* b_dec0   = (const float*)d_in[12];
    const float* W_dec1   = (const float*)d_in[13];
    const float* b_dec1   = (const float*)d_in[14];
    const float* W_out    = (const float*)d_in[15];
    const float* b_out    = (const float*)d_in[16];
    float* out = (float*)d_out;

    __half *xh, *h0h, *h1h, *zh, *d1h, *d2h;
    __half *we0, *we1, *whd, *wd0, *wd1, *wo;
    cudaGetSymbolAddress((void**)&xh, g_xh);
    cudaGetSymbolAddress((void**)&h0h, g_h0h);
    cudaGetSymbolAddress((void**)&h1h, g_h1h);
    cudaGetSymbolAddress((void**)&zh, g_zh);
    cudaGetSymbolAddress((void**)&d1h, g_d1h);
    cudaGetSymbolAddress((void**)&d2h, g_d2h);
    cudaGetSymbolAddress((void**)&we0, g_we0);
    cudaGetSymbolAddress((void**)&we1, g_we1);
    cudaGetSymbolAddress((void**)&whd, g_whd);
    cudaGetSymbolAddress((void**)&wd0, g_wd0);
    cudaGetSymbolAddress((void**)&wd1, g_wd1);
    cudaGetSymbolAddress((void**)&wo, g_wo);

    cudaFuncSetAttribute(hmma_gemm_k<0, true>,  cudaFuncAttributeMaxDynamicSharedMemorySize, SMEM_BYTES);
    cudaFuncSetAttribute(hmma_gemm_k<0, false>, cudaFuncAttributeMaxDynamicSharedMemorySize, SMEM_BYTES);
    cudaFuncSetAttribute(hmma_gemm_k<1, false>, cudaFuncAttributeMaxDynamicSharedMemorySize, SMEM_BYTES);
    cudaFuncSetAttribute(hmma_gemm_k<2, false>, cudaFuncAttributeMaxDynamicSharedMemorySize, SMEM_BYTES);

    // lazy static stream/events (created on uncaptured correctness call)
    static cudaStream_t s2 = nullptr;
    static cudaEvent_t ev_start = nullptr, ev_we0 = nullptr, ev_rest = nullptr;
    if (!s2) {
        cudaStreamCreateWithFlags(&s2, cudaStreamNonBlocking);
        cudaEventCreateWithFlags(&ev_start, cudaEventDisableTiming);
        cudaEventCreateWithFlags(&ev_we0,   cudaEventDisableTiming);
        cudaEventCreateWithFlags(&ev_rest,  cudaEventDisableTiming);
    }

    // fork: weight conversions on s2, routing/gather on default stream
    cudaEventRecord(ev_start, 0);
    cudaStreamWaitEvent(s2, ev_start, 0);

    tsplit_k<<<dim3(H0 / 32, DIN / 32, NC), dim3(32, 8), 0, s2>>>(W_enc0, we0, DIN, H0);
    cudaEventRecord(ev_we0, s2);
    tsplit_k<<<dim3(H0 / 32, H1 / 32, NC), dim3(32, 8), 0, s2>>>(W_dec1, wd1, H1, H0);
    tsplit_k<<<dim3(H1 / 32, H0 / 32, 1), dim3(32, 8), 0, s2>>>(W_enc1, we1, H0, H1);
    tsplit_k<<<dim3(LAT / 32, H1 / 32, 1), dim3(32, 8), 0, s2>>>(W_mu, whd, H1, LAT);
    tsplit_k<<<dim3(LAT / 32, H1 / 32, 1), dim3(32, 8), 0, s2>>>(W_logvar, whd + LAT * H1, H1, LAT);
    tsplit_k<<<dim3(H1 / 32, LAT / 32, 1), dim3(32, 8), 0, s2>>>(W_dec0, wd0, LAT, H1);
    tsplit_k<<<dim3(DIN / 32, H0 / 32, 1), dim3(32, 8), 0, s2>>>(W_out, wo, H0, DIN);
    cudaEventRecord(ev_rest, s2);

    histbuild_k<<<1, NTHR>>>(labels);
    scattergather_k<<<Bsz, 128>>>(labels, x, eps);

    // encoder layer 0 (grouped) — needs we0 + gather
    cudaStreamWaitEvent(0, ev_we0, 0);
    hmma_gemm_k<0, true><<<GRID_P, NTHR, SMEM_BYTES>>>(
        xh, DIN, we0, (size_t)DIN * H0, b_enc0, H0,
        H0, DIN, 0, h0h, H0, nullptr);

    // join remaining conversions
    cudaStreamWaitEvent(0, ev_rest, 0);

    // encoder layer 1
    hmma_gemm_k<0, false><<<GRID_P, NTHR, SMEM_BYTES>>>(
        h0h, H0, we1, 0, b_enc1, 0,
        H1, H0, Bsz / TBM, h1h, H1, nullptr);

    // heads: g_hd = h1 @ [W_mu | W_logvar]
    hmma_gemm_k<1, false><<<GRID_P, NTHR, SMEM_BYTES>>>(
        h1h, H1, whd, 0, b_mu, 0,
        256, H1, Bsz / TBM, nullptr, 0, nullptr);

    // reparameterize + scatter mu/logvar + z fp16 (vectorized)
    latent_k<<<(Bsz * LAT / 4 + 255) / 256, 256>>>(b_mu, b_logvar, out);

    // decoder layer 0
    hmma_gemm_k<0, false><<<GRID_P, NTHR, SMEM_BYTES>>>(
        zh, LAT, wd0, 0, b_dec0, 0,
        H1, LAT, Bsz / TBM, d1h, H1, nullptr);

    // decoder layer 1 (grouped)
    hmma_gemm_k<0, true><<<GRID_P, NTHR, SMEM_BYTES>>>(
        d1h, H1, wd1, (size_t)H1 * H0, b_dec1, H0,
        H0, H1, 0, d2h, H0, nullptr);

    // output layer (scatter rows)
    hmma_gemm_k<2, false><<<GRID_P, NTHR, SMEM_BYTES>>>(
        d2h, H0, wo, 0, b_out, 0,
        DIN, H0, Bsz / TBM, nullptr, 0, out);

    (void)in_sizes; (void)n_in; (void)out_size;
}

// round 17
// speedup vs baseline: 1.6239x; 1.0765x over previous
#include <cuda_runtime.h>
#include <cuda_fp16.h>
#include <cstdint>
#include <math.h>

// ---------------- problem constants ----------------
#define Bsz   8192
#define DIN   2048
#define H0    1024
#define H1    512
#define LAT   128
#define NC    8

#define TBM 128
#define BN  128
#define KC  64
#define NTHR 256
#define MAX_TILES 96
#define GRID_P 296            // 2 CTAs per SM

#define T_ROW  144            // 128B data + 16B pad per k-chunk row
#define A_SZ   (TBM * T_ROW)  // 18432
#define B_SZ   (BN * T_ROW)   // 18432
#define STAGE  (A_SZ + B_SZ)  // 36864
#define SMEM_BYTES (3 * STAGE) // 110592 per CTA; x2 CTAs = 221184 <= 227KB/SM

// ---------------- device scratch ----------------
__device__ __align__(16) __half g_xh  [Bsz * DIN];
__device__ __align__(16) float  g_epsp[Bsz * LAT];
__device__ __align__(16) __half g_h0h [Bsz * H0];
__device__ __align__(16) __half g_h1h [Bsz * H1];
__device__ __align__(16) float  g_hd  [Bsz * 256];     // mu|logvar raw (permuted rows)
__device__ __align__(16) __half g_zh  [Bsz * LAT];
__device__ __align__(16) __half g_d1h [Bsz * H1];
__device__ __align__(16) __half g_d2h [Bsz * H0];

// transposed fp16 weights [N, K] per cluster
__device__ __align__(16) __half g_we0[NC * DIN * H0];
__device__ __align__(16) __half g_we1[H0 * H1];
__device__ __align__(16) __half g_whd[256 * H1];       // [mu;logvar] concat rows
__device__ __align__(16) __half g_wd0[H1 * LAT];
__device__ __align__(16) __half g_wd1[NC * H1 * H0];
__device__ __align__(16) __half g_wo [DIN * H0];

__device__ int g_segoff[NC + 1];
__device__ int g_fill[NC];
__device__ int g_perm[Bsz];

struct Tile { int row_start; int row_end; int cluster; };
__device__ Tile g_tiles[MAX_TILES];
__device__ int  g_ntiles;

// ---------------- helpers ----------------
__device__ __forceinline__ uint32_t smem_u32(const void* p) {
    return (uint32_t)__cvta_generic_to_shared(p);
}
__device__ __forceinline__ void cp16(uint32_t saddr, const void* gptr) {
    asm volatile("cp.async.cg.shared.global [%0], [%1], 16;"
                 :: "r"(saddr), "l"(__cvta_generic_to_global(gptr)) : "memory");
}
__device__ __forceinline__ void cp_commit() {
    asm volatile("cp.async.commit_group;" ::: "memory");
}
template<int N> __device__ __forceinline__ void cp_wait() {
    asm volatile("cp.async.wait_group %0;" :: "n"(N) : "memory");
}
__device__ __forceinline__ void ldsm4(uint32_t a, uint32_t* r) {
    asm volatile("ldmatrix.sync.aligned.m8n8.x4.shared.b16 {%0,%1,%2,%3}, [%4];"
                 : "=r"(r[0]), "=r"(r[1]), "=r"(r[2]), "=r"(r[3]) : "r"(a));
}
__device__ __forceinline__ void mma16816(float* c, const uint32_t* a, const uint32_t* b) {
    asm volatile("mma.sync.aligned.m16n8k16.row.col.f32.f16.f16.f32 "
                 "{%0,%1,%2,%3}, {%4,%5,%6,%7}, {%8,%9}, {%0,%1,%2,%3};"
                 : "+f"(c[0]), "+f"(c[1]), "+f"(c[2]), "+f"(c[3])
                 : "r"(a[0]), "r"(a[1]), "r"(a[2]), "r"(a[3]), "r"(b[0]), "r"(b[1]));
}

// ---------------- setup kernels ----------------
__global__ void histbuild_k(const int* __restrict__ labels) {
    __shared__ int scnt[NC];
    int t = threadIdx.x;
    if (t < NC) scnt[t] = 0;
    __syncthreads();
    for (int i = t; i < Bsz; i += NTHR) atomicAdd(&scnt[labels[i]], 1);
    __syncthreads();
    if (t == 0) {
        int off = 0;
        for (int c = 0; c < NC; c++) {
            g_segoff[c] = off; g_fill[c] = 0; off += scnt[c];
        }
        g_segoff[NC] = off;
        int tt = 0;
        for (int c = 0; c < NC; c++) {
            int s = g_segoff[c], e = g_segoff[c + 1];
            for (int r = s; r < e; r += TBM) {
                g_tiles[tt].row_start = r;
                g_tiles[tt].row_end   = min(r + TBM, e);
                g_tiles[tt].cluster   = c;
                tt++;
            }
        }
        g_ntiles = tt;
    }
}

// fused: compute permuted position for source row + gather/convert row
__global__ void scattergather_k(const int* __restrict__ labels,
                                const float* __restrict__ x, const float* __restrict__ eps) {
    __shared__ int spos;
    int r = blockIdx.x;
    if (threadIdx.x == 0) {
        int c = labels[r];
        int pos = g_segoff[c] + atomicAdd(&g_fill[c], 1);
        g_perm[pos] = r;
        spos = pos;
    }
    __syncthreads();
    int pos = spos;
    const float4* xs = reinterpret_cast<const float4*>(x + (size_t)r * DIN);
    size_t dbase = (size_t)pos * DIN;
    for (int j = threadIdx.x; j < DIN / 4; j += blockDim.x) {
        float4 v = xs[j];
        __half2* dh = reinterpret_cast<__half2*>(g_xh + dbase + 4 * (size_t)j);
        dh[0] = __floats2half2_rn(v.x, v.y);
        dh[1] = __floats2half2_rn(v.z, v.w);
    }
    if (threadIdx.x < LAT / 4) {
        reinterpret_cast<float4*>(g_epsp + (size_t)pos * LAT)[threadIdx.x] =
            reinterpret_cast<const float4*>(eps + (size_t)r * LAT)[threadIdx.x];
    }
}

// transpose + convert, vectorized: W [K,N] fp32 -> Wt [N,K] fp16
// 64x64 tiles, float2 loads, half2 stores. Same per-element math as before.
__global__ void tsplit_k(const float* __restrict__ W,
                         __half* __restrict__ hi,
                         int K, int N) {
    __shared__ float t[64][65];
    int c = blockIdx.z;
    const float* Wc = W + (size_t)c * K * N;
    __half* hic = hi + (size_t)c * K * N;
    int n0 = blockIdx.x * 64, k0 = blockIdx.y * 64;
    int tx = threadIdx.x;        // 0..31
    int ty = threadIdx.y;        // 0..7
    // load: rows k0+i, cols n0 + 2*tx .. +1
    for (int i = ty; i < 64; i += 8) {
        float2 v = *reinterpret_cast<const float2*>(Wc + (size_t)(k0 + i) * N + n0 + 2 * tx);
        t[i][2 * tx]     = v.x;
        t[i][2 * tx + 1] = v.y;
    }
    __syncthreads();
    // store: Wt row n0+i, cols k0 + 2*tx .. +1  (= W[k0+2tx][n0+i], W[k0+2tx+1][n0+i])
    for (int i = ty; i < 64; i += 8) {
        __half2 h;
        h.x = __float2half(t[2 * tx][i]);
        h.y = __float2half(t[2 * tx + 1][i]);
        *reinterpret_cast<__half2*>(hic + (size_t)(n0 + i) * K + k0 + 2 * tx) = h;
    }
}

// ---------------- persistent HMMA fp16 GEMM, 2 CTAs/SM ----------------
// CTA tile 128x128, 8 warps (4m x 2n, warp 32x64), 3-stage cp.async pipeline.
// EPI: 0 = relu + fp16 store; 1 = raw fp32 to g_hd; 2 = +bias, scatter fp32 to out
template<int EPI, bool GROUPED>
__global__ __launch_bounds__(NTHR, 2)
void hmma_gemm_k(const __half* __restrict__ A, int lda,
                 const __half* __restrict__ W, size_t wstride,
                 const float* __restrict__ bias, int bstride,
                 int N, int K, int mtiles_in,
                 __half* __restrict__ O, int ldo,
                 float* __restrict__ out)
{
    extern __shared__ char smem[];
    uint32_t sb = smem_u32(smem);
    int tid  = threadIdx.x;
    int lane = tid & 31;
    int wid  = tid >> 5;
    int wm = (wid >> 1) * 32;    // 4 warps in m (tile 128)
    int wn = (wid & 1) * 64;     // 2 warps in n (tile 128)

    int mtiles = GROUPED ? g_ntiles : mtiles_in;
    int ncols  = N / BN;
    int total  = ncols * mtiles;
    int nk = K / KC;

    int arow = ((lane >> 3) & 1) * 8 + (lane & 7);
    int acol = (lane >> 4) * 16;
    int brow = ((lane >> 4) & 1) * 8 + (lane & 7);
    int bcol = ((lane >> 3) & 1) * 16;

    for (int t = blockIdx.x; t < total; t += gridDim.x) {
        int ncol = t / mtiles;
        int mti  = t - ncol * mtiles;
        int row0, row_end, c;
        if (GROUPED) {
            Tile tl = g_tiles[mti];
            row0 = tl.row_start; row_end = tl.row_end; c = tl.cluster;
        } else {
            row0 = mti * TBM; row_end = row0 + TBM; c = 0;
        }
        int n0 = ncol * BN;

        const __half* Wc = W + (size_t)c * wstride;

        float acc[2][8][4];
        #pragma unroll
        for (int a = 0; a < 2; a++)
            #pragma unroll
            for (int b = 0; b < 8; b++)
                #pragma unroll
                for (int d = 0; d < 4; d++) acc[a][b][d] = 0.f;

        auto issue = [&](int i) {
            int st = i % 3;
            uint32_t base = sb + (uint32_t)st * STAGE;
            int k0 = i * KC;
            #pragma unroll
            for (int it = 0; it < 4; it++) {
                int chunk = tid + it * NTHR;
                int row = chunk >> 3, c16 = chunk & 7;
                uint32_t soff = (uint32_t)(row * T_ROW + c16 * 16);
                int gr = row0 + row;
                if (GROUPED && gr >= Bsz) gr = Bsz - 1;
                size_t ga = (size_t)gr * lda + k0 + c16 * 8;
                cp16(base + soff, A + ga);
            }
            #pragma unroll
            for (int it = 0; it < 4; it++) {
                int chunk = tid + it * NTHR;
                int row = chunk >> 3, c16 = chunk & 7;
                uint32_t soff = (uint32_t)(row * T_ROW + c16 * 16);
                size_t gb = (size_t)(n0 + row) * K + k0 + c16 * 8;
                cp16(base + A_SZ + soff, Wc + gb);
            }
            cp_commit();
        };

        issue(0);
        if (nk > 1) issue(1);

        for (int i = 0; i < nk; i++) {
            if (i == nk - 1) cp_wait<0>(); else cp_wait<1>();
            // barrier: data of chunk i visible; all warps done with chunk i-1
            // -> safe for issue(i+2) to overwrite stage (i+2)%3 == (i-1)%3
            __syncthreads();
            if (i + 2 < nk) issue(i + 2);
            uint32_t base = sb + (uint32_t)(i % 3) * STAGE;

            #pragma unroll
            for (int kk = 0; kk < KC / 16; kk++) {
                uint32_t ah[2][4], bh[4][4];
                #pragma unroll
                for (int mt = 0; mt < 2; mt++) {
                    uint32_t ra = base + (uint32_t)((wm + mt * 16 + arow) * T_ROW + kk * 32 + acol);
                    ldsm4(ra, ah[mt]);
                }
                #pragma unroll
                for (int p = 0; p < 4; p++) {
                    uint32_t rb = base + A_SZ + (uint32_t)((wn + p * 16 + brow) * T_ROW + kk * 32 + bcol);
                    ldsm4(rb, bh[p]);
                }
                #pragma unroll
                for (int mt = 0; mt < 2; mt++)
                    #pragma unroll
                    for (int p = 0; p < 4; p++) {
                        mma16816(acc[mt][2 * p],     ah[mt], &bh[p][0]);
                        mma16816(acc[mt][2 * p + 1], ah[mt], &bh[p][2]);
                    }
            }
        }

        // ---------------- epilogue (registers + global only) ----------------
        int gid = lane >> 2, tig = lane & 3;
        const float* bc = bias + c * bstride;

        #pragma unroll
        for (int mt = 0; mt < 2; mt++) {
            int mA = row0 + wm + mt * 16 + gid;
            int mB = mA + 8;
            bool vA = !GROUPED || (mA < row_end);
            bool vB = !GROUPED || (mB < row_end);
            int oA = 0, oB = 0;
            if (EPI == 2) { oA = g_perm[mA]; oB = g_perm[mB]; }

            #pragma unroll
            for (int nt = 0; nt < 8; nt++) {
                int n = n0 + wn + nt * 8 + 2 * tig;
                float* a = acc[mt][nt];
                if (EPI == 0) {
                    float b0 = bc[n], b1 = bc[n + 1];
                    if (vA) {
                        float v0 = fmaxf(a[0] + b0, 0.f), v1 = fmaxf(a[1] + b1, 0.f);
                        *reinterpret_cast<__half2*>(O + (size_t)mA * ldo + n) = __floats2half2_rn(v0, v1);
                    }
                    if (vB) {
                        float v2 = fmaxf(a[2] + b0, 0.f), v3 = fmaxf(a[3] + b1, 0.f);
                        *reinterpret_cast<__half2*>(O + (size_t)mB * ldo + n) = __floats2half2_rn(v2, v3);
                    }
                } else if (EPI == 1) {
                    float2 p0; p0.x = a[0]; p0.y = a[1];
                    float2 p1; p1.x = a[2]; p1.y = a[3];
                    *reinterpret_cast<float2*>(&g_hd[(size_t)mA * 256 + n]) = p0;
                    *reinterpret_cast<float2*>(&g_hd[(size_t)mB * 256 + n]) = p1;
                } else {
                    float b0 = bc[n], b1 = bc[n + 1];
                    float2 p0; p0.x = a[0] + b0; p0.y = a[1] + b1;
                    float2 p1; p1.x = a[2] + b0; p1.y = a[3] + b1;
                    __stcs(reinterpret_cast<float2*>(out + (size_t)oA * DIN + n), p0);
                    __stcs(reinterpret_cast<float2*>(out + (size_t)oB * DIN + n), p1);
                }
            }
        }
        // stage-reuse guard before next tile's prefetch
        __syncthreads();
    }
}

// ---------------- latent: bias + reparameterize + scatter mu/logvar, z->fp16 ----
// vectorized: 4 latent elems per thread (float4 over g_hd / g_epsp)
__global__ void latent_k(const float* __restrict__ bmu, const float* __restrict__ blv,
                         float* __restrict__ out) {
    int idx = blockIdx.x * blockDim.x + threadIdx.x;   // over Bsz*LAT/4
    if (idx >= Bsz * LAT / 4) return;
    int r  = idx >> 5;          // LAT/4 = 32 quads per row
    int q  = idx & 31;
    int j  = q * 4;
    float4 mu4 = *reinterpret_cast<const float4*>(&g_hd[(size_t)r * 256 + j]);
    float4 lv4 = *reinterpret_cast<const float4*>(&g_hd[(size_t)r * 256 + 128 + j]);
    float4 bm  = *reinterpret_cast<const float4*>(bmu + j);
    float4 bl  = *reinterpret_cast<const float4*>(blv + j);
    float4 ep  = *reinterpret_cast<const float4*>(&g_epsp[(size_t)r * LAT + j]);
    mu4.x += bm.x; mu4.y += bm.y; mu4.z += bm.z; mu4.w += bm.w;
    lv4.x += bl.x; lv4.y += bl.y; lv4.z += bl.z; lv4.w += bl.w;
    float z0 = mu4.x + ep.x * expf(0.5f * lv4.x);
    float z1 = mu4.y + ep.y * expf(0.5f * lv4.y);
    float z2 = mu4.z + ep.z * expf(0.5f * lv4.z);
    float z3 = mu4.w + ep.w * expf(0.5f * lv4.w);
    __half2* zp = reinterpret_cast<__half2*>(&g_zh[(size_t)r * LAT + j]);
    zp[0] = __floats2half2_rn(z0, z1);
    zp[1] = __floats2half2_rn(z2, z3);
    int orow = g_perm[r];
    size_t OFF_MU = (size_t)Bsz * DIN;
    size_t OFF_LV = OFF_MU + (size_t)Bsz * LAT;
    *reinterpret_cast<float4*>(out + OFF_MU + (size_t)orow * LAT + j) = mu4;
    *reinterpret_cast<float4*>(out + OFF_LV + (size_t)orow * LAT + j) = lv4;
}

// ---------------- launcher ----------------
extern "C" void kernel_launch(void* const* d_in, const int* in_sizes, int n_in,
                              void* d_out, int out_size)
{
    const float* x        = (const float*)d_in[0];
    const int*   labels   = (const int*)  d_in[1];
    const float* eps      = (const float*)d_in[2];
    const float* W_enc0   = (const float*)d_in[3];
    const float* b_enc0   = (const float*)d_in[4];
    const float* W_enc1   = (const float*)d_in[5];
    const float* b_enc1   = (const float*)d_in[6];
    const float* W_mu     = (const float*)d_in[7];
    const float* b_mu     = (const float*)d_in[8];
    const float* W_logvar = (const float*)d_in[9];
    const float* b_logvar = (const float*)d_in[10];
    const float* W_dec0   = (const float*)d_in[11];
    const float* b_dec0   = (const float*)d_in[12];
    const float* W_dec1   = (const float*)d_in[13];
    const float* b_dec1   = (const float*)d_in[14];
    const float* W_out    = (const float*)d_in[15];
    const float* b_out    = (const float*)d_in[16];
    float* out = (float*)d_out;

    __half *xh, *h0h, *h1h, *zh, *d1h, *d2h;
    __half *we0, *we1, *whd, *wd0, *wd1, *wo;
    cudaGetSymbolAddress((void**)&xh, g_xh);
    cudaGetSymbolAddress((void**)&h0h, g_h0h);
    cudaGetSymbolAddress((void**)&h1h, g_h1h);
    cudaGetSymbolAddress((void**)&zh, g_zh);
    cudaGetSymbolAddress((void**)&d1h, g_d1h);
    cudaGetSymbolAddress((void**)&d2h, g_d2h);
    cudaGetSymbolAddress((void**)&we0, g_we0);
    cudaGetSymbolAddress((void**)&we1, g_we1);
    cudaGetSymbolAddress((void**)&whd, g_whd);
    cudaGetSymbolAddress((void**)&wd0, g_wd0);
    cudaGetSymbolAddress((void**)&wd1, g_wd1);
    cudaGetSymbolAddress((void**)&wo, g_wo);

    cudaFuncSetAttribute(hmma_gemm_k<0, true>,  cudaFuncAttributeMaxDynamicSharedMemorySize, SMEM_BYTES);
    cudaFuncSetAttribute(hmma_gemm_k<0, false>, cudaFuncAttributeMaxDynamicSharedMemorySize, SMEM_BYTES);
    cudaFuncSetAttribute(hmma_gemm_k<1, false>, cudaFuncAttributeMaxDynamicSharedMemorySize, SMEM_BYTES);
    cudaFuncSetAttribute(hmma_gemm_k<2, false>, cudaFuncAttributeMaxDynamicSharedMemorySize, SMEM_BYTES);

    // lazy static stream/events (created on uncaptured correctness call)
    static cudaStream_t s2 = nullptr;
    static cudaEvent_t ev_start = nullptr, ev_we0 = nullptr, ev_rest = nullptr;
    if (!s2) {
        cudaStreamCreateWithFlags(&s2, cudaStreamNonBlocking);
        cudaEventCreateWithFlags(&ev_start, cudaEventDisableTiming);
        cudaEventCreateWithFlags(&ev_we0,   cudaEventDisableTiming);
        cudaEventCreateWithFlags(&ev_rest,  cudaEventDisableTiming);
    }

    // fork: weight conversions on s2, routing/gather on default stream
    cudaEventRecord(ev_start, 0);
    cudaStreamWaitEvent(s2, ev_start, 0);

    tsplit_k<<<dim3(H0 / 64, DIN / 64, NC), dim3(32, 8), 0, s2>>>(W_enc0, we0, DIN, H0);
    cudaEventRecord(ev_we0, s2);
    tsplit_k<<<dim3(H0 / 64, H1 / 64, NC), dim3(32, 8), 0, s2>>>(W_dec1, wd1, H1, H0);
    tsplit_k<<<dim3(H1 / 64, H0 / 64, 1), dim3(32, 8), 0, s2>>>(W_enc1, we1, H0, H1);
    tsplit_k<<<dim3(LAT / 64, H1 / 64, 1), dim3(32, 8), 0, s2>>>(W_mu, whd, H1, LAT);
    tsplit_k<<<dim3(LAT / 64, H1 / 64, 1), dim3(32, 8), 0, s2>>>(W_logvar, whd + LAT * H1, H1, LAT);
    tsplit_k<<<dim3(H1 / 64, LAT / 64, 1), dim3(32, 8), 0, s2>>>(W_dec0, wd0, LAT, H1);
    tsplit_k<<<dim3(DIN / 64, H0 / 64, 1), dim3(32, 8), 0, s2>>>(W_out, wo, H0, DIN);
    cudaEventRecord(ev_rest, s2);

    histbuild_k<<<1, NTHR>>>(labels);
    scattergather_k<<<Bsz, 128>>>(labels, x, eps);

    // encoder layer 0 (grouped) — needs we0 + gather
    cudaStreamWaitEvent(0, ev_we0, 0);
    hmma_gemm_k<0, true><<<GRID_P, NTHR, SMEM_BYTES>>>(
        xh, DIN, we0, (size_t)DIN * H0, b_enc0, H0,
        H0, DIN, 0, h0h, H0, nullptr);

    // join remaining conversions
    cudaStreamWaitEvent(0, ev_rest, 0);

    // encoder layer 1
    hmma_gemm_k<0, false><<<GRID_P, NTHR, SMEM_BYTES>>>(
        h0h, H0, we1, 0, b_enc1, 0,
        H1, H0, Bsz / TBM, h1h, H1, nullptr);

    // heads: g_hd = h1 @ [W_mu | W_logvar]
    hmma_gemm_k<1, false><<<GRID_P, NTHR, SMEM_BYTES>>>(
        h1h, H1, whd, 0, b_mu, 0,
        256, H1, Bsz / TBM, nullptr, 0, nullptr);

    // reparameterize + scatter mu/logvar + z fp16 (vectorized)
    latent_k<<<(Bsz * LAT / 4 + 255) / 256, 256>>>(b_mu, b_logvar, out);

    // decoder layer 0
    hmma_gemm_k<0, false><<<GRID_P, NTHR, SMEM_BYTES>>>(
        zh, LAT, wd0, 0, b_dec0, 0,
        H1, LAT, Bsz / TBM, d1h, H1, nullptr);

    // decoder layer 1 (grouped)
    hmma_gemm_k<0, true><<<GRID_P, NTHR, SMEM_BYTES>>>(
        d1h, H1, wd1, (size_t)H1 * H0, b_dec1, H0,
        H0, H1, 0, d2h, H0, nullptr);

    // output layer (scatter rows)
    hmma_gemm_k<2, false><<<GRID_P, NTHR, SMEM_BYTES>>>(
        d2h, H0, wo, 0, b_out, 0,
        DIN, H0, Bsz / TBM, nullptr, 0, out);

    (void)in_sizes; (void)n_in; (void)out_size;
}